// round 8
// baseline (speedup 1.0000x reference)
#include <cuda_runtime.h>

#define NMAX 100000
#define EMAX 1600000
#define FULL 0xffffffffu

// ---------------- scratch (module-static, no runtime allocation) ----------------
__device__ __align__(16) float g_h1[NMAX * 64];    // layer1 linear output  [N,8,8]
__device__ __align__(16) float g_asrc1[NMAX * 8];  // per-node src attention, layer1
__device__ __align__(16) float g_adst1[NMAX * 8];  // per-node dst attention, layer1
__device__ __align__(16) float g_hl1[NMAX * 64];   // layer1 output post-ELU
__device__ __align__(16) float g_h2[NMAX * 40];    // layer2 linear output
__device__ __align__(16) float g_asrc2[NMAX];
__device__ __align__(16) float g_adst2[NMAX];
__device__ __align__(16) int   g_deg[NMAX];
__device__ __align__(16) int   g_off[NMAX];
__device__ __align__(16) int   g_cur[NMAX];
__device__ __align__(16) int   g_esrc[EMAX];       // src node of each dst-sorted edge
__device__ __align__(16) int   g_aux[128];         // scan block sums
__device__ int g_is64;                             // edge_index dtype flag

// ---------------- K0: detect edge_index dtype ----------------
// int64 data with values in [0,N): every odd 32-bit word (high half) is 0.
// int32 data: odd words are real node indices, OR over ~2048 of them != 0.
__global__ void k_detect(const unsigned int* __restrict__ w, int E) {
    int t = threadIdx.x;
    unsigned int acc = 0;
    int sample = min(2 * E, 4096);
    for (int i = 2 * t + 1; i < sample; i += 2 * blockDim.x) acc |= w[i];
#pragma unroll
    for (int d = 16; d; d >>= 1) acc |= __shfl_xor_sync(FULL, acc, d);
    __shared__ unsigned int s[8];
    if ((t & 31) == 0) s[t >> 5] = acc;
    __syncthreads();
    if (t == 0) {
        unsigned int a = 0;
        for (int i = 0; i < 8; i++) a |= s[i];
        g_is64 = (a == 0) ? 1 : 0;
    }
}

__device__ __forceinline__ int edge_at(const void* base, int pos, int N) {
    int v;
    if (g_is64) v = (int)((const long long*)base)[pos];
    else        v = ((const int*)base)[pos];
    // clamp: valid data makes this a no-op; invalid data degrades to a clean
    // wrong-answer instead of an address-space trap.
    return min(max(v, 0), N - 1);
}

// ---------------- K1: h1 = x @ W1, fused attention dots ----------------
// block: 128 nodes x 64 cols, 256 threads, thread = 4 nodes x 8 cols (one head)
__global__ void k_gemm1(const float* __restrict__ x, const float* __restrict__ W1,
                        const float* __restrict__ attS, const float* __restrict__ attD,
                        int N) {
    __shared__ float xs[128 * 33];
    __shared__ float ws[32 * 64];
    int t = threadIdx.x;
    int h = t & 7, ng = t >> 3;
    int warp = t >> 5, lane = t & 31;
    int n0b = blockIdx.x * 128;

    float acc[4][8];
#pragma unroll
    for (int i = 0; i < 4; i++)
#pragma unroll
        for (int c = 0; c < 8; c++) acc[i][c] = 0.f;

    for (int kc = 0; kc < 128; kc += 32) {
#pragma unroll
        for (int i = 0; i < 16; i++) {
            int row = warp * 16 + i;
            int n = n0b + row;
            xs[row * 33 + lane] = (n < N) ? x[n * 128 + kc + lane] : 0.f;
        }
#pragma unroll
        for (int i = 0; i < 8; i++) {
            int idx = t + i * 256;  // 2048 = 32*64
            ws[idx] = W1[kc * 64 + idx];
        }
        __syncthreads();
#pragma unroll
        for (int kk = 0; kk < 32; kk++) {
            float xv[4];
#pragma unroll
            for (int i = 0; i < 4; i++) xv[i] = xs[(ng * 4 + i) * 33 + kk];
            float wv[8];
#pragma unroll
            for (int c = 0; c < 8; c++) wv[c] = ws[kk * 64 + h * 8 + c];
#pragma unroll
            for (int i = 0; i < 4; i++)
#pragma unroll
                for (int c = 0; c < 8; c++) acc[i][c] += xv[i] * wv[c];
        }
        __syncthreads();
    }

    float as[8], ad[8];
#pragma unroll
    for (int c = 0; c < 8; c++) { as[c] = attS[h * 8 + c]; ad[c] = attD[h * 8 + c]; }
#pragma unroll
    for (int i = 0; i < 4; i++) {
        int n = n0b + ng * 4 + i;
        if (n < N) {
            float sa = 0.f, sd = 0.f;
#pragma unroll
            for (int c = 0; c < 8; c++) { sa += acc[i][c] * as[c]; sd += acc[i][c] * ad[c]; }
            g_asrc1[n * 8 + h] = sa;
            g_adst1[n * 8 + h] = sd;
#pragma unroll
            for (int c = 0; c < 8; c++) g_h1[n * 64 + h * 8 + c] = acc[i][c];
        }
    }
}

// ---------------- CSR build (dtype-agnostic via g_is64) ----------------
__global__ void k_zero_deg(int N) {
    int i = blockIdx.x * blockDim.x + threadIdx.x;
    if (i < N) g_deg[i] = 0;
}

__global__ void k_count(const void* __restrict__ ei, int E, int N) {
    int e = blockIdx.x * blockDim.x + threadIdx.x;
    if (e < E) atomicAdd(&g_deg[edge_at(ei, E + e, N)], 1);
}

// block scans 1024 elements (256 thr x 4)
__global__ void k_scan1(int N) {
    __shared__ int wsum[8];
    int t = threadIdx.x;
    int base = blockIdx.x * 1024;
    int lane = t & 31, warp = t >> 5;
    int v[4];
    int s = 0;
#pragma unroll
    for (int i = 0; i < 4; i++) {
        int idx = base + t * 4 + i;
        v[i] = (idx < N) ? g_deg[idx] : 0;
        s += v[i];
    }
    int inc = s;
#pragma unroll
    for (int d = 1; d < 32; d <<= 1) {
        int o = __shfl_up_sync(FULL, inc, d);
        if (lane >= d) inc += o;
    }
    if (lane == 31) wsum[warp] = inc;
    __syncthreads();
    if (warp == 0 && lane < 8) {
        int wv = wsum[lane];
        int winc = wv;
#pragma unroll
        for (int d = 1; d < 8; d <<= 1) {
            int o = __shfl_up_sync(0x000000ffu, winc, d);
            if (lane >= d) winc += o;
        }
        wsum[lane] = winc - wv;               // exclusive
        if (lane == 7) g_aux[blockIdx.x] = winc;  // block total
    }
    __syncthreads();
    int excl = wsum[warp] + inc - s;
#pragma unroll
    for (int i = 0; i < 4; i++) {
        int idx = base + t * 4 + i;
        if (idx < N) { g_off[idx] = excl; excl += v[i]; }
    }
}

__global__ void k_scan2(int nb) {  // 1 block, 128 threads, nb <= 128
    __shared__ int ws[4];
    int t = threadIdx.x;
    int lane = t & 31, warp = t >> 5;
    int v = (t < nb) ? g_aux[t] : 0;
    int inc = v;
#pragma unroll
    for (int d = 1; d < 32; d <<= 1) {
        int o = __shfl_up_sync(FULL, inc, d);
        if (lane >= d) inc += o;
    }
    if (lane == 31) ws[warp] = inc;
    __syncthreads();
    int add = 0;
    for (int w = 0; w < warp; w++) add += ws[w];
    int excl = add + inc - v;
    if (t < nb) g_aux[t] = excl;
}

__global__ void k_scan3(int N) {
    int i = blockIdx.x * blockDim.x + threadIdx.x;
    if (i < N) {
        g_off[i] += g_aux[i >> 10];
        g_cur[i] = 0;
    }
}

__global__ void k_scatter(const void* __restrict__ ei, int E, int N) {
    int e = blockIdx.x * blockDim.x + threadIdx.x;
    if (e < E) {
        int d = edge_at(ei, E + e, N);
        int pos = g_off[d] + atomicAdd(&g_cur[d], 1);
        pos = min(max(pos, 0), E - 1);
        g_esrc[pos] = edge_at(ei, e, N);
    }
}

// ---------------- K3: layer-1 softmax aggregation + bias + ELU ----------------
// one warp per destination node; lane owns output channels {lane, lane+32}
__global__ void k_agg1(const float* __restrict__ b1, int N) {
    int lane = threadIdx.x & 31;
    int node = blockIdx.x * 8 + (threadIdx.x >> 5);
    if (node >= N) return;
    int start = g_off[node];
    int cnt = g_deg[node] + 1;  // +1 self-loop (processed as edge j==0)

    // pass 1: softmax denominator; lane = (edge-in-group g, head h)
    int g = lane >> 3, h = lane & 7;
    float adst_h = g_adst1[node * 8 + h];
    float psum = 0.f;
    for (int j = g; j < cnt; j += 4) {
        int s = (j == 0) ? node : g_esrc[start + j - 1];
        float e = g_asrc1[s * 8 + h] + adst_h;
        e = (e > 0.f) ? e : 0.2f * e;
        psum += __expf(e);
    }
    psum += __shfl_xor_sync(FULL, psum, 8);
    psum += __shfl_xor_sync(FULL, psum, 16);  // lanes with head h hold s[h]

    int ha = lane >> 3, hb = ha + 4;  // heads of channels lane / lane+32
    float inva = 1.f / __shfl_sync(FULL, psum, ha);
    float invb = 1.f / __shfl_sync(FULL, psum, hb);
    float adA = g_adst1[node * 8 + ha];
    float adB = g_adst1[node * 8 + hb];

    // pass 2: weighted accumulation
    float acc0 = 0.f, acc1 = 0.f;
    for (int base = 0; base < cnt; base += 32) {
        int m = min(32, cnt - base);
        int j = base + lane;
        int mysrc = 0;
        if (lane < m) mysrc = (j == 0) ? node : g_esrc[start + j - 1];
        for (int jj = 0; jj < m; jj++) {
            int s = __shfl_sync(FULL, mysrc, jj);
            float ea = g_asrc1[s * 8 + ha] + adA; ea = (ea > 0.f) ? ea : 0.2f * ea;
            float eb = g_asrc1[s * 8 + hb] + adB; eb = (eb > 0.f) ? eb : 0.2f * eb;
            float pa = __expf(ea) * inva;
            float pb = __expf(eb) * invb;
            acc0 += pa * g_h1[s * 64 + lane];
            acc1 += pb * g_h1[s * 64 + 32 + lane];
        }
    }
    float v0 = acc0 + b1[lane];
    float v1 = acc1 + b1[32 + lane];
    v0 = (v0 > 0.f) ? v0 : (__expf(v0) - 1.f);  // ELU
    v1 = (v1 > 0.f) ? v1 : (__expf(v1) - 1.f);
    g_hl1[node * 64 + lane] = v0;
    g_hl1[node * 64 + 32 + lane] = v1;
}

// ---------------- K4: h2 = hl1 @ W2, fused attention dots ----------------
// block: 128 nodes x 40 cols, 256 threads, thread = 4 nodes x 5 cols
__global__ void k_gemm2(const float* __restrict__ W2, const float* __restrict__ attS,
                        const float* __restrict__ attD, int N) {
    __shared__ float xs[128 * 33];
    __shared__ float ws[32 * 40];
    int t = threadIdx.x;
    int cg = t & 7, ng = t >> 3;
    int warp = t >> 5, lane = t & 31;
    int n0b = blockIdx.x * 128;

    float acc[4][5];
#pragma unroll
    for (int i = 0; i < 4; i++)
#pragma unroll
        for (int c = 0; c < 5; c++) acc[i][c] = 0.f;

    for (int kc = 0; kc < 64; kc += 32) {
#pragma unroll
        for (int i = 0; i < 16; i++) {
            int row = warp * 16 + i;
            int n = n0b + row;
            xs[row * 33 + lane] = (n < N) ? g_hl1[n * 64 + kc + lane] : 0.f;
        }
        for (int idx = t; idx < 32 * 40; idx += 256) ws[idx] = W2[kc * 40 + idx];
        __syncthreads();
#pragma unroll
        for (int kk = 0; kk < 32; kk++) {
            float xv[4];
#pragma unroll
            for (int i = 0; i < 4; i++) xv[i] = xs[(ng * 4 + i) * 33 + kk];
            float wv[5];
#pragma unroll
            for (int c = 0; c < 5; c++) wv[c] = ws[kk * 40 + cg * 5 + c];
#pragma unroll
            for (int i = 0; i < 4; i++)
#pragma unroll
                for (int c = 0; c < 5; c++) acc[i][c] += xv[i] * wv[c];
        }
        __syncthreads();
    }

    float as[5], ad[5];
#pragma unroll
    for (int c = 0; c < 5; c++) { as[c] = attS[cg * 5 + c]; ad[c] = attD[cg * 5 + c]; }
#pragma unroll
    for (int i = 0; i < 4; i++) {
        int n = n0b + ng * 4 + i;
        float sa = 0.f, sd = 0.f;
#pragma unroll
        for (int c = 0; c < 5; c++) { sa += acc[i][c] * as[c]; sd += acc[i][c] * ad[c]; }
#pragma unroll
        for (int d = 1; d < 8; d <<= 1) {  // reduce across the 8 col-groups
            sa += __shfl_xor_sync(FULL, sa, d);
            sd += __shfl_xor_sync(FULL, sd, d);
        }
        if (n < N) {
#pragma unroll
            for (int c = 0; c < 5; c++) g_h2[n * 40 + cg * 5 + c] = acc[i][c];
            if (cg == 0) { g_asrc2[n] = sa; g_adst2[n] = sd; }
        }
    }
}

// ---------------- K5: layer-2 aggregation + log_softmax ----------------
__global__ void k_agg2(const float* __restrict__ b2, float* __restrict__ out, int N) {
    int lane = threadIdx.x & 31;
    int node = blockIdx.x * 8 + (threadIdx.x >> 5);
    if (node >= N) return;
    int start = g_off[node];
    int cnt = g_deg[node] + 1;
    float adst = g_adst2[node];

    float psum = 0.f;
    for (int j = lane; j < cnt; j += 32) {
        int s = (j == 0) ? node : g_esrc[start + j - 1];
        float e = g_asrc2[s] + adst;
        e = (e > 0.f) ? e : 0.2f * e;
        psum += __expf(e);
    }
#pragma unroll
    for (int d = 16; d; d >>= 1) psum += __shfl_xor_sync(FULL, psum, d);
    float inv = 1.f / psum;

    float acc0 = 0.f, acc1 = 0.f;
    for (int base = 0; base < cnt; base += 32) {
        int m = min(32, cnt - base);
        int j = base + lane;
        int mysrc = 0;
        if (lane < m) mysrc = (j == 0) ? node : g_esrc[start + j - 1];
        for (int jj = 0; jj < m; jj++) {
            int s = __shfl_sync(FULL, mysrc, jj);
            float e = g_asrc2[s] + adst;
            e = (e > 0.f) ? e : 0.2f * e;
            float al = __expf(e) * inv;
            acc0 += al * g_h2[s * 40 + lane];
            if (lane < 8) acc1 += al * g_h2[s * 40 + 32 + lane];
        }
    }
    float v0 = acc0 + b2[lane];
    float v1 = (lane < 8) ? (acc1 + b2[32 + lane]) : -1e30f;

    float mx = fmaxf(v0, v1);
#pragma unroll
    for (int d = 16; d; d >>= 1) mx = fmaxf(mx, __shfl_xor_sync(FULL, mx, d));
    float se = __expf(v0 - mx) + ((lane < 8) ? __expf(v1 - mx) : 0.f);
#pragma unroll
    for (int d = 16; d; d >>= 1) se += __shfl_xor_sync(FULL, se, d);
    float ls = __logf(se) + mx;

    out[node * 40 + lane] = v0 - ls;
    if (lane < 8) out[node * 40 + 32 + lane] = v1 - ls;
}

// ---------------- launch ----------------
extern "C" void kernel_launch(void* const* d_in, const int* in_sizes, int n_in,
                              void* d_out, int out_size) {
    const float* x   = (const float*)d_in[0];
    const void*  ei  = d_in[1];                 // int32 or int64, detected on device
    const float* W1  = (const float*)d_in[2];
    const float* aS1 = (const float*)d_in[3];
    const float* aD1 = (const float*)d_in[4];
    const float* b1  = (const float*)d_in[5];
    const float* W2  = (const float*)d_in[6];
    const float* aS2 = (const float*)d_in[7];
    const float* aD2 = (const float*)d_in[8];
    const float* b2  = (const float*)d_in[9];
    float* out = (float*)d_out;

    int N = in_sizes[0] / 128;
    int E = in_sizes[1] / 2;
    int nb1024 = (N + 1023) / 1024;

    k_detect<<<1, 256>>>((const unsigned int*)ei, E);
    k_gemm1<<<(N + 127) / 128, 256>>>(x, W1, aS1, aD1, N);
    k_zero_deg<<<(N + 255) / 256, 256>>>(N);
    k_count<<<(E + 255) / 256, 256>>>(ei, E, N);
    k_scan1<<<nb1024, 256>>>(N);
    k_scan2<<<1, 128>>>(nb1024);
    k_scan3<<<(N + 255) / 256, 256>>>(N);
    k_scatter<<<(E + 255) / 256, 256>>>(ei, E, N);
    k_agg1<<<(N + 7) / 8, 256>>>(b1, N);
    k_gemm2<<<(N + 127) / 128, 256>>>(W2, aS2, aD2, N);
    k_agg2<<<(N + 7) / 8, 256>>>(b2, out, N);
}

// round 9
// speedup vs baseline: 1.0134x; 1.0134x over previous
#include <cuda_runtime.h>

#define NMAX 100000
#define EMAX 1600000
#define FULL 0xffffffffu

// ---------------- scratch ----------------
__device__ __align__(16) float g_h1[NMAX * 64];
__device__ __align__(16) float g_asrc1[NMAX * 8];
__device__ __align__(16) float g_adst1[NMAX * 8];
__device__ __align__(16) float g_hl1[NMAX * 64];
__device__ __align__(16) float g_h2[NMAX * 40];
__device__ __align__(16) float g_asrc2[NMAX];
__device__ __align__(16) float g_adst2[NMAX];
__device__ __align__(16) int   g_deg[NMAX];
__device__ __align__(16) int   g_off[NMAX];
__device__ __align__(16) int   g_cur[NMAX];
__device__ __align__(16) int   g_esrc[EMAX];
__device__ __align__(16) int   g_aux[128];
__device__ int g_is64;

// ---------------- K0: dtype detect ----------------
__global__ void k_detect(const unsigned int* __restrict__ w, int E) {
    int t = threadIdx.x;
    unsigned int acc = 0;
    int sample = min(2 * E, 4096);
    for (int i = 2 * t + 1; i < sample; i += 2 * blockDim.x) acc |= w[i];
#pragma unroll
    for (int d = 16; d; d >>= 1) acc |= __shfl_xor_sync(FULL, acc, d);
    __shared__ unsigned int s[8];
    if ((t & 31) == 0) s[t >> 5] = acc;
    __syncthreads();
    if (t == 0) {
        unsigned int a = 0;
        for (int i = 0; i < 8; i++) a |= s[i];
        g_is64 = (a == 0) ? 1 : 0;
    }
}

__device__ __forceinline__ int edge_at(const void* base, int pos, int N) {
    int v;
    if (g_is64) v = (int)((const long long*)base)[pos];
    else        v = ((const int*)base)[pos];
    return min(max(v, 0), N - 1);
}

// ---------------- K1: h1 = x @ W1 (+ attention dots), float4 staging ----------------
__global__ void k_gemm1(const float* __restrict__ x, const float* __restrict__ W1,
                        const float* __restrict__ attS, const float* __restrict__ attD,
                        int N) {
    __shared__ __align__(16) float xs[128 * 36];
    __shared__ __align__(16) float ws[32 * 64];
    int t = threadIdx.x;
    int h = t & 7, ng = t >> 3;
    int n0b = blockIdx.x * 128;

    float acc[4][8];
#pragma unroll
    for (int i = 0; i < 4; i++)
#pragma unroll
        for (int c = 0; c < 8; c++) acc[i][c] = 0.f;

    for (int kc = 0; kc < 128; kc += 32) {
        // stage x chunk: 128 rows x 32 cols via float4
#pragma unroll
        for (int i = 0; i < 4; i++) {
            int idx = t + i * 256;            // 0..1023
            int row = idx >> 3, q = idx & 7;  // 8 float4 per row
            int n = n0b + row;
            float4 v = make_float4(0.f, 0.f, 0.f, 0.f);
            if (n < N) v = *(const float4*)(x + n * 128 + kc + q * 4);
            *(float4*)(xs + row * 36 + q * 4) = v;
        }
        // stage W chunk: 32x64 via float4
#pragma unroll
        for (int i = 0; i < 2; i++) {
            int idx = t + i * 256;            // 0..511 float4s
            *(float4*)(ws + idx * 4) = *(const float4*)(W1 + kc * 64 + idx * 4);
        }
        __syncthreads();
#pragma unroll
        for (int kk = 0; kk < 32; kk++) {
            float xv[4];
#pragma unroll
            for (int i = 0; i < 4; i++) xv[i] = xs[(ng * 4 + i) * 36 + kk];
            float4 w0 = *(const float4*)(ws + kk * 64 + h * 8);
            float4 w1 = *(const float4*)(ws + kk * 64 + h * 8 + 4);
#pragma unroll
            for (int i = 0; i < 4; i++) {
                acc[i][0] += xv[i] * w0.x; acc[i][1] += xv[i] * w0.y;
                acc[i][2] += xv[i] * w0.z; acc[i][3] += xv[i] * w0.w;
                acc[i][4] += xv[i] * w1.x; acc[i][5] += xv[i] * w1.y;
                acc[i][6] += xv[i] * w1.z; acc[i][7] += xv[i] * w1.w;
            }
        }
        __syncthreads();
    }

    float as[8], ad[8];
#pragma unroll
    for (int c = 0; c < 8; c++) { as[c] = attS[h * 8 + c]; ad[c] = attD[h * 8 + c]; }
#pragma unroll
    for (int i = 0; i < 4; i++) {
        int n = n0b + ng * 4 + i;
        if (n < N) {
            float sa = 0.f, sd = 0.f;
#pragma unroll
            for (int c = 0; c < 8; c++) { sa += acc[i][c] * as[c]; sd += acc[i][c] * ad[c]; }
            g_asrc1[n * 8 + h] = sa;
            g_adst1[n * 8 + h] = sd;
            *(float4*)(g_h1 + n * 64 + h * 8) = make_float4(acc[i][0], acc[i][1], acc[i][2], acc[i][3]);
            *(float4*)(g_h1 + n * 64 + h * 8 + 4) = make_float4(acc[i][4], acc[i][5], acc[i][6], acc[i][7]);
        }
    }
}

// ---------------- CSR build ----------------
__global__ void k_zero(int N) {
    int i = blockIdx.x * blockDim.x + threadIdx.x;
    if (i < N) { g_deg[i] = 0; g_cur[i] = 0; }
}

__global__ void k_count(const void* __restrict__ ei, int E, int N) {
    int base = (blockIdx.x * blockDim.x + threadIdx.x) * 4;
#pragma unroll
    for (int k = 0; k < 4; k++) {
        int e = base + k;
        if (e < E) atomicAdd(&g_deg[edge_at(ei, E + e, N)], 1);
    }
}

__global__ void k_scan1(int N) {
    __shared__ int wsum[8];
    int t = threadIdx.x;
    int base = blockIdx.x * 1024;
    int lane = t & 31, warp = t >> 5;
    int v[4];
    int s = 0;
#pragma unroll
    for (int i = 0; i < 4; i++) {
        int idx = base + t * 4 + i;
        v[i] = (idx < N) ? g_deg[idx] : 0;
        s += v[i];
    }
    int inc = s;
#pragma unroll
    for (int d = 1; d < 32; d <<= 1) {
        int o = __shfl_up_sync(FULL, inc, d);
        if (lane >= d) inc += o;
    }
    if (lane == 31) wsum[warp] = inc;
    __syncthreads();
    if (warp == 0 && lane < 8) {
        int wv = wsum[lane];
        int winc = wv;
#pragma unroll
        for (int d = 1; d < 8; d <<= 1) {
            int o = __shfl_up_sync(0x000000ffu, winc, d);
            if (lane >= d) winc += o;
        }
        wsum[lane] = winc - wv;
        if (lane == 7) g_aux[blockIdx.x] = winc;
    }
    __syncthreads();
    int excl = wsum[warp] + inc - s;
#pragma unroll
    for (int i = 0; i < 4; i++) {
        int idx = base + t * 4 + i;
        if (idx < N) { g_off[idx] = excl; excl += v[i]; }
    }
}

__global__ void k_scan2(int nb) {
    __shared__ int ws[4];
    int t = threadIdx.x;
    int lane = t & 31, warp = t >> 5;
    int v = (t < nb) ? g_aux[t] : 0;
    int inc = v;
#pragma unroll
    for (int d = 1; d < 32; d <<= 1) {
        int o = __shfl_up_sync(FULL, inc, d);
        if (lane >= d) inc += o;
    }
    if (lane == 31) ws[warp] = inc;
    __syncthreads();
    int add = 0;
    for (int w = 0; w < warp; w++) add += ws[w];
    int excl = add + inc - v;
    if (t < nb) g_aux[t] = excl;
}

__global__ void k_scan3(int N) {
    int i = blockIdx.x * blockDim.x + threadIdx.x;
    if (i < N) g_off[i] += g_aux[i >> 10];
}

__global__ void k_scatter(const void* __restrict__ ei, int E, int N) {
    int base = (blockIdx.x * blockDim.x + threadIdx.x) * 4;
#pragma unroll
    for (int k = 0; k < 4; k++) {
        int e = base + k;
        if (e < E) {
            int d = edge_at(ei, E + e, N);
            int pos = g_off[d] + atomicAdd(&g_cur[d], 1);
            pos = min(max(pos, 0), E - 1);
            g_esrc[pos] = edge_at(ei, e, N);
        }
    }
}

// ---------------- K3: layer-1 aggregation, single pass, smem alpha ----------------
// warp per node; lane owns channels {lane, lane+32}; post-hoc normalization
__global__ void k_agg1(const float* __restrict__ b1, int N) {
    __shared__ __align__(16) float sal[8][8 * 33];  // [warp][h*33+edge]
    int lane = threadIdx.x & 31;
    int w = threadIdx.x >> 5;
    int node = blockIdx.x * 8 + w;
    if (node >= N) return;
    int start = g_off[node];
    int cnt = g_deg[node] + 1;  // self-loop at j==0

    float ad[8];
#pragma unroll
    for (int h = 0; h < 8; h++) ad[h] = g_adst1[node * 8 + h];

    int ha = lane >> 3, hb = ha + 4;
    float acc0 = 0.f, acc1 = 0.f;
    float hs[8];
#pragma unroll
    for (int h = 0; h < 8; h++) hs[h] = 0.f;

    for (int base = 0; base < cnt; base += 32) {
        int m = min(32, cnt - base);
        int j = base + lane;
        int mysrc = 0;
        if (lane < m) {
            mysrc = (j == 0) ? node : g_esrc[start + j - 1];
            float4 a0 = *(const float4*)(g_asrc1 + mysrc * 8);
            float4 a1 = *(const float4*)(g_asrc1 + mysrc * 8 + 4);
            float av[8] = {a0.x, a0.y, a0.z, a0.w, a1.x, a1.y, a1.z, a1.w};
#pragma unroll
            for (int h = 0; h < 8; h++) {
                float e = av[h] + ad[h];
                e = (e > 0.f) ? e : 0.2f * e;
                float ex = __expf(e);
                sal[w][h * 33 + lane] = ex;
                hs[h] += ex;
            }
        }
        __syncwarp();
        for (int jj = 0; jj < m; jj++) {
            int s = __shfl_sync(FULL, mysrc, jj);
            float pa = sal[w][ha * 33 + jj];
            float pb = sal[w][hb * 33 + jj];
            acc0 += pa * g_h1[s * 64 + lane];
            acc1 += pb * g_h1[s * 64 + 32 + lane];
        }
        __syncwarp();
    }

    // reduce per-head sums across lanes
#pragma unroll
    for (int h = 0; h < 8; h++) {
        float v = hs[h];
#pragma unroll
        for (int d = 16; d; d >>= 1) v += __shfl_xor_sync(FULL, v, d);
        hs[h] = v;
    }
    float sA = (ha < 2) ? (ha == 0 ? hs[0] : hs[1]) : (ha == 2 ? hs[2] : hs[3]);
    float sB = (ha < 2) ? (ha == 0 ? hs[4] : hs[5]) : (ha == 2 ? hs[6] : hs[7]);

    float v0 = acc0 / sA + b1[lane];
    float v1 = acc1 / sB + b1[32 + lane];
    v0 = (v0 > 0.f) ? v0 : (__expf(v0) - 1.f);
    v1 = (v1 > 0.f) ? v1 : (__expf(v1) - 1.f);
    g_hl1[node * 64 + lane] = v0;
    g_hl1[node * 64 + 32 + lane] = v1;
}

// ---------------- K4: h2 = hl1 @ W2 (+ attention dots) ----------------
__global__ void k_gemm2(const float* __restrict__ W2, const float* __restrict__ attS,
                        const float* __restrict__ attD, int N) {
    __shared__ float xs[128 * 33];
    __shared__ float ws[32 * 40];
    int t = threadIdx.x;
    int cg = t & 7, ng = t >> 3;
    int warp = t >> 5, lane = t & 31;
    int n0b = blockIdx.x * 128;

    float acc[4][5];
#pragma unroll
    for (int i = 0; i < 4; i++)
#pragma unroll
        for (int c = 0; c < 5; c++) acc[i][c] = 0.f;

    for (int kc = 0; kc < 64; kc += 32) {
#pragma unroll
        for (int i = 0; i < 16; i++) {
            int row = warp * 16 + i;
            int n = n0b + row;
            xs[row * 33 + lane] = (n < N) ? g_hl1[n * 64 + kc + lane] : 0.f;
        }
        for (int idx = t; idx < 32 * 40; idx += 256) ws[idx] = W2[kc * 40 + idx];
        __syncthreads();
#pragma unroll
        for (int kk = 0; kk < 32; kk++) {
            float xv[4];
#pragma unroll
            for (int i = 0; i < 4; i++) xv[i] = xs[(ng * 4 + i) * 33 + kk];
            float wv[5];
#pragma unroll
            for (int c = 0; c < 5; c++) wv[c] = ws[kk * 40 + cg * 5 + c];
#pragma unroll
            for (int i = 0; i < 4; i++)
#pragma unroll
                for (int c = 0; c < 5; c++) acc[i][c] += xv[i] * wv[c];
        }
        __syncthreads();
    }

    float as[5], ad[5];
#pragma unroll
    for (int c = 0; c < 5; c++) { as[c] = attS[cg * 5 + c]; ad[c] = attD[cg * 5 + c]; }
#pragma unroll
    for (int i = 0; i < 4; i++) {
        int n = n0b + ng * 4 + i;
        float sa = 0.f, sd = 0.f;
#pragma unroll
        for (int c = 0; c < 5; c++) { sa += acc[i][c] * as[c]; sd += acc[i][c] * ad[c]; }
#pragma unroll
        for (int d = 1; d < 8; d <<= 1) {
            sa += __shfl_xor_sync(FULL, sa, d);
            sd += __shfl_xor_sync(FULL, sd, d);
        }
        if (n < N) {
#pragma unroll
            for (int c = 0; c < 5; c++) g_h2[n * 40 + cg * 5 + c] = acc[i][c];
            if (cg == 0) { g_asrc2[n] = sa; g_adst2[n] = sd; }
        }
    }
}

// ---------------- K5: layer-2 aggregation + log_softmax, single pass ----------------
__global__ void k_agg2(const float* __restrict__ b2, float* __restrict__ out, int N) {
    int lane = threadIdx.x & 31;
    int node = blockIdx.x * 8 + (threadIdx.x >> 5);
    if (node >= N) return;
    int start = g_off[node];
    int cnt = g_deg[node] + 1;
    float adst = g_adst2[node];

    float acc0 = 0.f, acc1 = 0.f, ps = 0.f;
    for (int base = 0; base < cnt; base += 32) {
        int m = min(32, cnt - base);
        int j = base + lane;
        int mysrc = 0;
        float myal = 0.f;
        if (lane < m) {
            mysrc = (j == 0) ? node : g_esrc[start + j - 1];
            float e = g_asrc2[mysrc] + adst;
            e = (e > 0.f) ? e : 0.2f * e;
            myal = __expf(e);
            ps += myal;
        }
        for (int jj = 0; jj < m; jj++) {
            int s = __shfl_sync(FULL, mysrc, jj);
            float al = __shfl_sync(FULL, myal, jj);
            acc0 += al * g_h2[s * 40 + lane];
            if (lane < 8) acc1 += al * g_h2[s * 40 + 32 + lane];
        }
    }
#pragma unroll
    for (int d = 16; d; d >>= 1) ps += __shfl_xor_sync(FULL, ps, d);
    float inv = 1.f / ps;

    float v0 = acc0 * inv + b2[lane];
    float v1 = (lane < 8) ? (acc1 * inv + b2[32 + lane]) : -1e30f;

    float mx = fmaxf(v0, v1);
#pragma unroll
    for (int d = 16; d; d >>= 1) mx = fmaxf(mx, __shfl_xor_sync(FULL, mx, d));
    float se = __expf(v0 - mx) + ((lane < 8) ? __expf(v1 - mx) : 0.f);
#pragma unroll
    for (int d = 16; d; d >>= 1) se += __shfl_xor_sync(FULL, se, d);
    float ls = __logf(se) + mx;

    out[node * 40 + lane] = v0 - ls;
    if (lane < 8) out[node * 40 + 32 + lane] = v1 - ls;
}

// ---------------- launch ----------------
extern "C" void kernel_launch(void* const* d_in, const int* in_sizes, int n_in,
                              void* d_out, int out_size) {
    const float* x   = (const float*)d_in[0];
    const void*  ei  = d_in[1];
    const float* W1  = (const float*)d_in[2];
    const float* aS1 = (const float*)d_in[3];
    const float* aD1 = (const float*)d_in[4];
    const float* b1  = (const float*)d_in[5];
    const float* W2  = (const float*)d_in[6];
    const float* aS2 = (const float*)d_in[7];
    const float* aD2 = (const float*)d_in[8];
    const float* b2  = (const float*)d_in[9];
    float* out = (float*)d_out;

    int N = in_sizes[0] / 128;
    int E = in_sizes[1] / 2;
    int nb1024 = (N + 1023) / 1024;
    int ebq = (E + 1023) / 1024;   // edge blocks, 4 edges/thread

    k_detect<<<1, 256>>>((const unsigned int*)ei, E);
    k_gemm1<<<(N + 127) / 128, 256>>>(x, W1, aS1, aD1, N);
    k_zero<<<(N + 255) / 256, 256>>>(N);
    k_count<<<ebq, 256>>>(ei, E, N);
    k_scan1<<<nb1024, 256>>>(N);
    k_scan2<<<1, 128>>>(nb1024);
    k_scan3<<<(N + 255) / 256, 256>>>(N);
    k_scatter<<<ebq, 256>>>(ei, E, N);
    k_agg1<<<(N + 7) / 8, 256>>>(b1, N);
    k_gemm2<<<(N + 127) / 128, 256>>>(W2, aS2, aD2, N);
    k_agg2<<<(N + 7) / 8, 256>>>(b2, out, N);
}

// round 10
// speedup vs baseline: 1.0689x; 1.0548x over previous
#include <cuda_runtime.h>

#define NMAX 100000
#define EMAX 1600000
#define FULL 0xffffffffu

// ---------------- scratch ----------------
__device__ __align__(16) float g_h1[NMAX * 64];
__device__ __align__(16) float g_asrc1[NMAX * 8];
__device__ __align__(16) float g_adst1[NMAX * 8];
__device__ __align__(16) float g_hl1[NMAX * 64];
__device__ __align__(16) float g_h2[NMAX * 40];
__device__ __align__(16) float g_asrc2[NMAX];
__device__ __align__(16) float g_adst2[NMAX];
__device__ __align__(16) int   g_deg[NMAX];
__device__ __align__(16) int   g_off[NMAX];
__device__ __align__(16) int   g_cur[NMAX];
__device__ __align__(16) int   g_esrc[EMAX];
__device__ __align__(16) int   g_aux[128];
__device__ int g_is64;

// ---------------- K0: zero counters + detect dtype (block 0) ----------------
__global__ void k_zero_detect(const unsigned int* __restrict__ w, int E, int N) {
    int i = blockIdx.x * blockDim.x + threadIdx.x;
    if (i < N) { g_deg[i] = 0; g_cur[i] = 0; }
    if (blockIdx.x == 0) {
        int t = threadIdx.x;
        unsigned int acc = 0;
        int sample = min(2 * E, 4096);
        for (int k = 2 * t + 1; k < sample; k += 2 * blockDim.x) acc |= w[k];
#pragma unroll
        for (int d = 16; d; d >>= 1) acc |= __shfl_xor_sync(FULL, acc, d);
        __shared__ unsigned int s[8];
        if ((t & 31) == 0) s[t >> 5] = acc;
        __syncthreads();
        if (t == 0) {
            unsigned int a = 0;
            for (int k = 0; k < 8; k++) a |= s[k];
            g_is64 = (a == 0) ? 1 : 0;
        }
    }
}

__device__ __forceinline__ int edge_at(const void* base, int pos, int N) {
    int v;
    if (g_is64) v = (int)((const long long*)base)[pos];
    else        v = ((const int*)base)[pos];
    return min(max(v, 0), N - 1);
}

// load 4 consecutive edge indices starting at pos (pos % 4 == 0)
__device__ __forceinline__ void edge4(const void* base, int pos, int N, int* out) {
    if (g_is64) {
        longlong2 a = ((const longlong2*)base)[pos >> 1];
        longlong2 b = ((const longlong2*)base)[(pos >> 1) + 1];
        out[0] = (int)a.x; out[1] = (int)a.y; out[2] = (int)b.x; out[3] = (int)b.y;
    } else {
        int4 v = *(const int4*)((const int*)base + pos);
        out[0] = v.x; out[1] = v.y; out[2] = v.z; out[3] = v.w;
    }
#pragma unroll
    for (int k = 0; k < 4; k++) out[k] = min(max(out[k], 0), N - 1);
}

// ---------------- K1: h1 = x @ W1 (+ attention dots), float4 staging ----------------
__global__ void k_gemm1(const float* __restrict__ x, const float* __restrict__ W1,
                        const float* __restrict__ attS, const float* __restrict__ attD,
                        int N) {
    __shared__ __align__(16) float xs[128 * 36];
    __shared__ __align__(16) float ws[32 * 64];
    int t = threadIdx.x;
    int h = t & 7, ng = t >> 3;
    int n0b = blockIdx.x * 128;

    float acc[4][8];
#pragma unroll
    for (int i = 0; i < 4; i++)
#pragma unroll
        for (int c = 0; c < 8; c++) acc[i][c] = 0.f;

    for (int kc = 0; kc < 128; kc += 32) {
#pragma unroll
        for (int i = 0; i < 4; i++) {
            int idx = t + i * 256;
            int row = idx >> 3, q = idx & 7;
            int n = n0b + row;
            float4 v = make_float4(0.f, 0.f, 0.f, 0.f);
            if (n < N) v = *(const float4*)(x + n * 128 + kc + q * 4);
            *(float4*)(xs + row * 36 + q * 4) = v;
        }
#pragma unroll
        for (int i = 0; i < 2; i++) {
            int idx = t + i * 256;
            *(float4*)(ws + idx * 4) = *(const float4*)(W1 + kc * 64 + idx * 4);
        }
        __syncthreads();
#pragma unroll
        for (int kk = 0; kk < 32; kk++) {
            float xv[4];
#pragma unroll
            for (int i = 0; i < 4; i++) xv[i] = xs[(ng * 4 + i) * 36 + kk];
            float4 w0 = *(const float4*)(ws + kk * 64 + h * 8);
            float4 w1 = *(const float4*)(ws + kk * 64 + h * 8 + 4);
#pragma unroll
            for (int i = 0; i < 4; i++) {
                acc[i][0] += xv[i] * w0.x; acc[i][1] += xv[i] * w0.y;
                acc[i][2] += xv[i] * w0.z; acc[i][3] += xv[i] * w0.w;
                acc[i][4] += xv[i] * w1.x; acc[i][5] += xv[i] * w1.y;
                acc[i][6] += xv[i] * w1.z; acc[i][7] += xv[i] * w1.w;
            }
        }
        __syncthreads();
    }

    float as[8], ad[8];
#pragma unroll
    for (int c = 0; c < 8; c++) { as[c] = attS[h * 8 + c]; ad[c] = attD[h * 8 + c]; }
#pragma unroll
    for (int i = 0; i < 4; i++) {
        int n = n0b + ng * 4 + i;
        if (n < N) {
            float sa = 0.f, sd = 0.f;
#pragma unroll
            for (int c = 0; c < 8; c++) { sa += acc[i][c] * as[c]; sd += acc[i][c] * ad[c]; }
            g_asrc1[n * 8 + h] = sa;
            g_adst1[n * 8 + h] = sd;
            *(float4*)(g_h1 + n * 64 + h * 8) = make_float4(acc[i][0], acc[i][1], acc[i][2], acc[i][3]);
            *(float4*)(g_h1 + n * 64 + h * 8 + 4) = make_float4(acc[i][4], acc[i][5], acc[i][6], acc[i][7]);
        }
    }
}

// ---------------- CSR build ----------------
__global__ void k_count(const void* __restrict__ ei, int E, int N) {
    int base = (blockIdx.x * blockDim.x + threadIdx.x) * 4;
    if (base + 3 < E) {
        int d[4];
        edge4(ei, E + base, N, d);
#pragma unroll
        for (int k = 0; k < 4; k++) atomicAdd(&g_deg[d[k]], 1);
    } else {
        for (int e = base; e < E; e++) atomicAdd(&g_deg[edge_at(ei, E + e, N)], 1);
    }
}

__global__ void k_scan1(int N) {
    __shared__ int wsum[8];
    int t = threadIdx.x;
    int base = blockIdx.x * 1024;
    int lane = t & 31, warp = t >> 5;
    int v[4];
    int s = 0;
#pragma unroll
    for (int i = 0; i < 4; i++) {
        int idx = base + t * 4 + i;
        v[i] = (idx < N) ? g_deg[idx] : 0;
        s += v[i];
    }
    int inc = s;
#pragma unroll
    for (int d = 1; d < 32; d <<= 1) {
        int o = __shfl_up_sync(FULL, inc, d);
        if (lane >= d) inc += o;
    }
    if (lane == 31) wsum[warp] = inc;
    __syncthreads();
    if (warp == 0 && lane < 8) {
        int wv = wsum[lane];
        int winc = wv;
#pragma unroll
        for (int d = 1; d < 8; d <<= 1) {
            int o = __shfl_up_sync(0x000000ffu, winc, d);
            if (lane >= d) winc += o;
        }
        wsum[lane] = winc - wv;
        if (lane == 7) g_aux[blockIdx.x] = winc;
    }
    __syncthreads();
    int excl = wsum[warp] + inc - s;
#pragma unroll
    for (int i = 0; i < 4; i++) {
        int idx = base + t * 4 + i;
        if (idx < N) { g_off[idx] = excl; excl += v[i]; }
    }
}

__global__ void k_scan2(int nb) {
    __shared__ int ws[4];
    int t = threadIdx.x;
    int lane = t & 31, warp = t >> 5;
    int v = (t < nb) ? g_aux[t] : 0;
    int inc = v;
#pragma unroll
    for (int d = 1; d < 32; d <<= 1) {
        int o = __shfl_up_sync(FULL, inc, d);
        if (lane >= d) inc += o;
    }
    if (lane == 31) ws[warp] = inc;
    __syncthreads();
    int add = 0;
    for (int w = 0; w < warp; w++) add += ws[w];
    int excl = add + inc - v;
    if (t < nb) g_aux[t] = excl;
}

__global__ void k_scan3(int N) {
    int i = blockIdx.x * blockDim.x + threadIdx.x;
    if (i < N) g_off[i] += g_aux[i >> 10];
}

__global__ void k_scatter(const void* __restrict__ ei, int E, int N) {
    int base = (blockIdx.x * blockDim.x + threadIdx.x) * 4;
    if (base + 3 < E) {
        int d[4], sv[4];
        edge4(ei, E + base, N, d);
        edge4(ei, base, N, sv);
#pragma unroll
        for (int k = 0; k < 4; k++) {
            int pos = g_off[d[k]] + atomicAdd(&g_cur[d[k]], 1);
            pos = min(max(pos, 0), E - 1);
            g_esrc[pos] = sv[k];
        }
    } else {
        for (int e = base; e < E; e++) {
            int d = edge_at(ei, E + e, N);
            int pos = g_off[d] + atomicAdd(&g_cur[d], 1);
            pos = min(max(pos, 0), E - 1);
            g_esrc[pos] = edge_at(ei, e, N);
        }
    }
}

// ---------------- K3: layer-1 aggregation, float2 channels ----------------
// warp per node; lane owns channels {2*lane, 2*lane+1} (same head ha=lane>>2)
__global__ void k_agg1(const float* __restrict__ b1, int N) {
    __shared__ __align__(16) float sal[8][8 * 33];  // [warp][h*33+edge]
    __shared__ float shs[8][8];                     // per-warp per-head sums
    int lane = threadIdx.x & 31;
    int w = threadIdx.x >> 5;
    int node = blockIdx.x * 8 + w;
    if (node >= N) return;
    int start = g_off[node];
    int cnt = g_deg[node] + 1;  // self-loop at j==0

    float ad[8];
    {
        float4 d0 = *(const float4*)(g_adst1 + node * 8);
        float4 d1 = *(const float4*)(g_adst1 + node * 8 + 4);
        ad[0] = d0.x; ad[1] = d0.y; ad[2] = d0.z; ad[3] = d0.w;
        ad[4] = d1.x; ad[5] = d1.y; ad[6] = d1.z; ad[7] = d1.w;
    }

    int ha = lane >> 2;
    float accx = 0.f, accy = 0.f;
    float hs[8];
#pragma unroll
    for (int h = 0; h < 8; h++) hs[h] = 0.f;

    for (int base = 0; base < cnt; base += 32) {
        int m = min(32, cnt - base);
        int j = base + lane;
        int mysrc = 0;
        if (lane < m) {
            mysrc = (j == 0) ? node : g_esrc[start + j - 1];
            float4 a0 = *(const float4*)(g_asrc1 + mysrc * 8);
            float4 a1 = *(const float4*)(g_asrc1 + mysrc * 8 + 4);
            float av[8] = {a0.x, a0.y, a0.z, a0.w, a1.x, a1.y, a1.z, a1.w};
#pragma unroll
            for (int h = 0; h < 8; h++) {
                float e = av[h] + ad[h];
                e = (e > 0.f) ? e : 0.2f * e;
                float ex = __expf(e);
                sal[w][h * 33 + lane] = ex;
                hs[h] += ex;
            }
        }
        __syncwarp();
        for (int jj = 0; jj < m; jj++) {
            int s = __shfl_sync(FULL, mysrc, jj);
            float pa = sal[w][ha * 33 + jj];
            float2 f = *(const float2*)(g_h1 + s * 64 + 2 * lane);
            accx += pa * f.x;
            accy += pa * f.y;
        }
        __syncwarp();
    }

    // reduce per-head exp sums across lanes, stash in smem
#pragma unroll
    for (int h = 0; h < 8; h++) {
        float v = hs[h];
#pragma unroll
        for (int d = 16; d; d >>= 1) v += __shfl_xor_sync(FULL, v, d);
        if (lane == 0) shs[w][h] = v;
    }
    __syncwarp();
    float inv = 1.f / shs[w][ha];

    float2 bv = *(const float2*)(b1 + 2 * lane);
    float v0 = accx * inv + bv.x;
    float v1 = accy * inv + bv.y;
    v0 = (v0 > 0.f) ? v0 : (__expf(v0) - 1.f);
    v1 = (v1 > 0.f) ? v1 : (__expf(v1) - 1.f);
    *(float2*)(g_hl1 + node * 64 + 2 * lane) = make_float2(v0, v1);
}

// ---------------- K4: h2 = hl1 @ W2 (+ attention dots) ----------------
__global__ void k_gemm2(const float* __restrict__ W2, const float* __restrict__ attS,
                        const float* __restrict__ attD, int N) {
    __shared__ float xs[128 * 33];
    __shared__ float ws[32 * 40];
    int t = threadIdx.x;
    int cg = t & 7, ng = t >> 3;
    int warp = t >> 5, lane = t & 31;
    int n0b = blockIdx.x * 128;

    float acc[4][5];
#pragma unroll
    for (int i = 0; i < 4; i++)
#pragma unroll
        for (int c = 0; c < 5; c++) acc[i][c] = 0.f;

    for (int kc = 0; kc < 64; kc += 32) {
#pragma unroll
        for (int i = 0; i < 16; i++) {
            int row = warp * 16 + i;
            int n = n0b + row;
            xs[row * 33 + lane] = (n < N) ? g_hl1[n * 64 + kc + lane] : 0.f;
        }
        for (int idx = t; idx < 32 * 40; idx += 256) ws[idx] = W2[kc * 40 + idx];
        __syncthreads();
#pragma unroll
        for (int kk = 0; kk < 32; kk++) {
            float xv[4];
#pragma unroll
            for (int i = 0; i < 4; i++) xv[i] = xs[(ng * 4 + i) * 33 + kk];
            float wv[5];
#pragma unroll
            for (int c = 0; c < 5; c++) wv[c] = ws[kk * 40 + cg * 5 + c];
#pragma unroll
            for (int i = 0; i < 4; i++)
#pragma unroll
                for (int c = 0; c < 5; c++) acc[i][c] += xv[i] * wv[c];
        }
        __syncthreads();
    }

    float as[5], ad[5];
#pragma unroll
    for (int c = 0; c < 5; c++) { as[c] = attS[cg * 5 + c]; ad[c] = attD[cg * 5 + c]; }
#pragma unroll
    for (int i = 0; i < 4; i++) {
        int n = n0b + ng * 4 + i;
        float sa = 0.f, sd = 0.f;
#pragma unroll
        for (int c = 0; c < 5; c++) { sa += acc[i][c] * as[c]; sd += acc[i][c] * ad[c]; }
#pragma unroll
        for (int d = 1; d < 8; d <<= 1) {
            sa += __shfl_xor_sync(FULL, sa, d);
            sd += __shfl_xor_sync(FULL, sd, d);
        }
        if (n < N) {
#pragma unroll
            for (int c = 0; c < 5; c++) g_h2[n * 40 + cg * 5 + c] = acc[i][c];
            if (cg == 0) { g_asrc2[n] = sa; g_adst2[n] = sd; }
        }
    }
}

// ---------------- K5: layer-2 aggregation + log_softmax, float2 channels ----------------
__global__ void k_agg2(const float* __restrict__ b2, float* __restrict__ out, int N) {
    int lane = threadIdx.x & 31;
    int node = blockIdx.x * 8 + (threadIdx.x >> 5);
    if (node >= N) return;
    int start = g_off[node];
    int cnt = g_deg[node] + 1;
    float adst = g_adst2[node];

    float accx = 0.f, accy = 0.f, ps = 0.f;
    for (int base = 0; base < cnt; base += 32) {
        int m = min(32, cnt - base);
        int j = base + lane;
        int mysrc = 0;
        float myal = 0.f;
        if (lane < m) {
            mysrc = (j == 0) ? node : g_esrc[start + j - 1];
            float e = g_asrc2[mysrc] + adst;
            e = (e > 0.f) ? e : 0.2f * e;
            myal = __expf(e);
            ps += myal;
        }
        for (int jj = 0; jj < m; jj++) {
            int s = __shfl_sync(FULL, mysrc, jj);
            float al = __shfl_sync(FULL, myal, jj);
            if (lane < 20) {
                float2 f = *(const float2*)(g_h2 + s * 40 + 2 * lane);
                accx += al * f.x;
                accy += al * f.y;
            }
        }
    }
#pragma unroll
    for (int d = 16; d; d >>= 1) ps += __shfl_xor_sync(FULL, ps, d);
    float inv = 1.f / ps;

    float v0 = -1e30f, v1 = -1e30f;
    if (lane < 20) {
        v0 = accx * inv + b2[2 * lane];
        v1 = accy * inv + b2[2 * lane + 1];
    }
    float mx = fmaxf(v0, v1);
#pragma unroll
    for (int d = 16; d; d >>= 1) mx = fmaxf(mx, __shfl_xor_sync(FULL, mx, d));
    float se = (lane < 20) ? (__expf(v0 - mx) + __expf(v1 - mx)) : 0.f;
#pragma unroll
    for (int d = 16; d; d >>= 1) se += __shfl_xor_sync(FULL, se, d);
    float ls = __logf(se) + mx;

    if (lane < 20)
        *(float2*)(out + node * 40 + 2 * lane) = make_float2(v0 - ls, v1 - ls);
}

// ---------------- launch ----------------
extern "C" void kernel_launch(void* const* d_in, const int* in_sizes, int n_in,
                              void* d_out, int out_size) {
    const float* x   = (const float*)d_in[0];
    const void*  ei  = d_in[1];
    const float* W1  = (const float*)d_in[2];
    const float* aS1 = (const float*)d_in[3];
    const float* aD1 = (const float*)d_in[4];
    const float* b1  = (const float*)d_in[5];
    const float* W2  = (const float*)d_in[6];
    const float* aS2 = (const float*)d_in[7];
    const float* aD2 = (const float*)d_in[8];
    const float* b2  = (const float*)d_in[9];
    float* out = (float*)d_out;

    int N = in_sizes[0] / 128;
    int E = in_sizes[1] / 2;
    int nb1024 = (N + 1023) / 1024;
    int ebq = (E + 1023) / 1024;

    k_zero_detect<<<(N + 255) / 256, 256>>>((const unsigned int*)ei, E, N);
    k_gemm1<<<(N + 127) / 128, 256>>>(x, W1, aS1, aD1, N);
    k_count<<<ebq, 256>>>(ei, E, N);
    k_scan1<<<nb1024, 256>>>(N);
    k_scan2<<<1, 128>>>(nb1024);
    k_scan3<<<(N + 255) / 256, 256>>>(N);
    k_scatter<<<ebq, 256>>>(ei, E, N);
    k_agg1<<<(N + 7) / 8, 256>>>(b1, N);
    k_gemm2<<<(N + 127) / 128, 256>>>(W2, aS2, aD2, N);
    k_agg2<<<(N + 7) / 8, 256>>>(b2, out, N);
}